// round 5
// baseline (speedup 1.0000x reference)
#include <cuda_runtime.h>
#include <math.h>

#define Bsz  32
#define Tlen 512
#define Idim 1024
#define Hdim 1024
#define G4   4096

// ---------------- device scratch ----------------
__device__ float g_xw[(size_t)Tlen * Bsz * G4];   // [t][b][4H]
__device__ float g_wt[(size_t)Idim * G4];         // W_ih transposed: [k][n]
__device__ float g_h2[2][Hdim * Bsz];             // pair-interleaved h: slot=(k>>1)*64+b*2+(k&1)
__device__ unsigned int g_bar;

// ---------------- helpers ----------------
__device__ __forceinline__ void fma2(unsigned long long& acc,
                                     unsigned long long a, unsigned long long b)
{
    asm volatile("fma.rn.f32x2 %0, %1, %2, %0;" : "+l"(acc) : "l"(a), "l"(b));
}
__device__ __forceinline__ unsigned long long pack2(float lo, float hi)
{
    unsigned long long r;
    asm("mov.b64 %0, {%1, %2};" : "=l"(r) : "f"(lo), "f"(hi));
    return r;
}
__device__ __forceinline__ void unpack2(unsigned long long p, float& lo, float& hi)
{
    asm("mov.b64 {%0, %1}, %2;" : "=f"(lo), "=f"(hi) : "l"(p));
}
__device__ __forceinline__ void lds_v2u64(unsigned addr,
                                          unsigned long long& a, unsigned long long& b)
{
    asm volatile("ld.shared.v2.u64 {%0, %1}, [%2];" : "=l"(a), "=l"(b) : "r"(addr));
}
__device__ __forceinline__ void cp_async16(unsigned dst, const void* src)
{
    asm volatile("cp.async.cg.shared.global [%0], [%1], 16;" :: "r"(dst), "l"(src));
}
#define CP_COMMIT()  asm volatile("cp.async.commit_group;")
#define CP_WAIT(N)   asm volatile("cp.async.wait_group %0;" :: "n"(N))

__device__ __forceinline__ unsigned long long ldcg_u64(const void* p)
{
    unsigned long long r;
    asm volatile("ld.global.cg.b64 %0, [%1];" : "=l"(r) : "l"(p));
    return r;
}
__device__ __forceinline__ void stcg_u64(void* p, unsigned long long v)
{
    asm volatile("st.global.cg.b64 [%0], %1;" :: "l"(p), "l"(v));
}

// inf-safe fast gates (tolerance is 1e-3; these are ~1e-7 accurate)
__device__ __forceinline__ float sig_fast(float x)
{
    return __frcp_rn(1.f + __expf(-x));
}
__device__ __forceinline__ float tanh_fast(float x)
{
    // 2*sigmoid(2x)-1 : e^{-2x}=inf -> rcp=0 -> -1 (no NaN)
    return fmaf(2.f, __frcp_rn(1.f + __expf(-2.f * x)), -1.f);
}

// =======================================================================
// Kernel 0: transpose W_ih -> g_wt[k][n]; also resets grid barrier.
// =======================================================================
__global__ void __launch_bounds__(256) transpose_wih_kernel(const float* __restrict__ W)
{
    __shared__ float tile[32][33];
    if (blockIdx.x == 0 && blockIdx.y == 0 && threadIdx.x == 0) g_bar = 0u;
    const int x  = threadIdx.x & 31;
    const int y4 = (threadIdx.x >> 5) << 2;
    const int nb = blockIdx.x * 32;
    const int kb = blockIdx.y * 32;
#pragma unroll
    for (int j = 0; j < 4; j++)
        tile[y4 + j][x] = W[(size_t)(nb + y4 + j) * Idim + kb + x];
    __syncthreads();
#pragma unroll
    for (int j = 0; j < 4; j++)
        g_wt[(size_t)(kb + y4 + j) * G4 + nb + x] = tile[x][y4 + j];
}

// =======================================================================
// Phase 1: g_xw = x @ Wih^T + b.  128x128 tile, BK=16, 256 threads,
// 8x8 microtile in f32x2. A staged pre-duplicated {a,a}; B via cp.async.
// =======================================================================
#define P1_BK 16

__global__ void __launch_bounds__(256, 2) gemm_xw_kernel(
    const float* __restrict__ x, const float* __restrict__ bias)
{
    __shared__ float As2[2][P1_BK][256];   // [k][2m dup]
    __shared__ float Bs [2][P1_BK][128];   // [k][n]

    const int tid  = threadIdx.x;
    const int bn   = blockIdx.x * 128;
    const int bm   = blockIdx.y * 128;
    const int tx8  = (tid & 15) << 3;
    const int ty8  = (tid >> 4) << 3;
    const int srow = tid >> 1;
    const int skq  = (tid & 1) << 3;
    const int kk   = tid & 15;
    const int seg  = tid >> 4;

    const unsigned as_base = (unsigned)__cvta_generic_to_shared(&As2[0][0][0]);
    const unsigned bs_base = (unsigned)__cvta_generic_to_shared(&Bs[0][0][0]);

    const float* Ag = x + (size_t)(bm + srow) * Idim + skq;

    float4 a0c = *(const float4*)(Ag + 0);
    float4 a1c = *(const float4*)(Ag + 4);
    {
        const float* bsrc = g_wt + (size_t)kk * G4 + bn + seg * 8;
        unsigned bdst = bs_base + (unsigned)(((kk) * 128 + seg * 8) * 4);
        cp_async16(bdst,      bsrc);
        cp_async16(bdst + 16, bsrc + 4);
        CP_COMMIT();
    }
    {
        float va[8] = {a0c.x, a0c.y, a0c.z, a0c.w, a1c.x, a1c.y, a1c.z, a1c.w};
#pragma unroll
        for (int j = 0; j < 8; j++)
            *(unsigned long long*)&As2[0][skq + j][2 * srow] = pack2(va[j], va[j]);
    }
    a0c = *(const float4*)(Ag + 16);
    a1c = *(const float4*)(Ag + 20);
    CP_WAIT(0);
    __syncthreads();

    unsigned long long acc[8][4];
#pragma unroll
    for (int i = 0; i < 8; i++)
#pragma unroll
        for (int j = 0; j < 4; j++) acc[i][j] = 0ull;

    int p = 0;
    for (int kt = 0; kt < Idim / P1_BK; kt++) {
        if (kt + 1 < Idim / P1_BK) {
            const float* bsrc = g_wt + (size_t)((kt + 1) * P1_BK + kk) * G4 + bn + seg * 8;
            unsigned bdst = bs_base +
                (unsigned)((((p ^ 1) * P1_BK + kk) * 128 + seg * 8) * 4);
            cp_async16(bdst,      bsrc);
            cp_async16(bdst + 16, bsrc + 4);
            CP_COMMIT();
            float va[8] = {a0c.x, a0c.y, a0c.z, a0c.w, a1c.x, a1c.y, a1c.z, a1c.w};
#pragma unroll
            for (int j = 0; j < 8; j++)
                *(unsigned long long*)&As2[p ^ 1][skq + j][2 * srow] = pack2(va[j], va[j]);
            if (kt + 2 < Idim / P1_BK) {
                a0c = *(const float4*)(Ag + (kt + 2) * P1_BK);
                a1c = *(const float4*)(Ag + (kt + 2) * P1_BK + 4);
            }
        }

#pragma unroll
        for (int k = 0; k < P1_BK; k++) {
            unsigned aaddr = as_base +
                (unsigned)(((p * P1_BK + k) * 256 + 2 * ty8) * 4);
            unsigned long long pa0, pa1, pa2, pa3, pa4, pa5, pa6, pa7;
            lds_v2u64(aaddr,      pa0, pa1);
            lds_v2u64(aaddr + 16, pa2, pa3);
            lds_v2u64(aaddr + 32, pa4, pa5);
            lds_v2u64(aaddr + 48, pa6, pa7);
            unsigned baddr = bs_base +
                (unsigned)(((p * P1_BK + k) * 128 + tx8) * 4);
            unsigned long long b0, b1, b2, b3;
            lds_v2u64(baddr,      b0, b1);
            lds_v2u64(baddr + 16, b2, b3);
            fma2(acc[0][0], pa0, b0); fma2(acc[0][1], pa0, b1);
            fma2(acc[0][2], pa0, b2); fma2(acc[0][3], pa0, b3);
            fma2(acc[1][0], pa1, b0); fma2(acc[1][1], pa1, b1);
            fma2(acc[1][2], pa1, b2); fma2(acc[1][3], pa1, b3);
            fma2(acc[2][0], pa2, b0); fma2(acc[2][1], pa2, b1);
            fma2(acc[2][2], pa2, b2); fma2(acc[2][3], pa2, b3);
            fma2(acc[3][0], pa3, b0); fma2(acc[3][1], pa3, b1);
            fma2(acc[3][2], pa3, b2); fma2(acc[3][3], pa3, b3);
            fma2(acc[4][0], pa4, b0); fma2(acc[4][1], pa4, b1);
            fma2(acc[4][2], pa4, b2); fma2(acc[4][3], pa4, b3);
            fma2(acc[5][0], pa5, b0); fma2(acc[5][1], pa5, b1);
            fma2(acc[5][2], pa5, b2); fma2(acc[5][3], pa5, b3);
            fma2(acc[6][0], pa6, b0); fma2(acc[6][1], pa6, b1);
            fma2(acc[6][2], pa6, b2); fma2(acc[6][3], pa6, b3);
            fma2(acc[7][0], pa7, b0); fma2(acc[7][1], pa7, b1);
            fma2(acc[7][2], pa7, b2); fma2(acc[7][3], pa7, b3);
        }

        if (kt + 1 < Idim / P1_BK) {
            CP_WAIT(0);
            __syncthreads();
            p ^= 1;
        }
    }

    float4 bb0 = *(const float4*)&bias[bn + tx8];
    float4 bb1 = *(const float4*)&bias[bn + tx8 + 4];
#pragma unroll
    for (int i = 0; i < 8; i++) {
        int m = bm + ty8 + i;
        int t = m & (Tlen - 1);
        int b = m >> 9;
        float4 o0, o1;
        unpack2(acc[i][0], o0.x, o0.y);
        unpack2(acc[i][1], o0.z, o0.w);
        unpack2(acc[i][2], o1.x, o1.y);
        unpack2(acc[i][3], o1.z, o1.w);
        o0.x += bb0.x; o0.y += bb0.y; o0.z += bb0.z; o0.w += bb0.w;
        o1.x += bb1.x; o1.y += bb1.y; o1.z += bb1.z; o1.w += bb1.w;
        float* dst = &g_xw[(size_t)t * (Bsz * G4) + (size_t)b * G4 + bn + tx8];
        *(float4*)(dst + 0) = o0;
        *(float4*)(dst + 4) = o1;
    }
}

// =======================================================================
// Phase 2: persistent recurrence. 128 blocks x 128 threads.
// Warp wi owns 2 h-cols (hc0=bid*8+wi*2, +1) x 4 gates; lane = batch.
// W_hh slice in SMEM (only thing in SMEM). h read DIRECTLY from L2 via
// ld.global.cg — no smem staging, no intra-step __syncthreads.
// =======================================================================
#define NBLK 128
#define SMEM_BYTES (32 * 1024 * 4)   // 128 KB W only

__device__ __forceinline__ void grid_barrier(unsigned target)
{
    __syncthreads();
    if (threadIdx.x == 0) {
        __threadfence();
        asm volatile("red.release.gpu.global.add.u32 [%0], %1;"
                     :: "l"(&g_bar), "r"(1u) : "memory");
        unsigned v;
        do {
            asm volatile("ld.acquire.gpu.global.u32 %0, [%1];"
                         : "=r"(v) : "l"(&g_bar) : "memory");
        } while (v < target);
    }
    __syncthreads();
}

__global__ void __launch_bounds__(128, 1) lstm_rec_kernel(
    const float* __restrict__ Whh, float* __restrict__ out)
{
    extern __shared__ float smem[];
    float* sw = smem;                    // [32 rows][1024]
    const int tid  = threadIdx.x;
    const int bid  = blockIdx.x;
    const int wi   = tid >> 5;
    const int lane = tid & 31;
    const int hc0  = (bid << 3) + (wi << 1);

    const unsigned sw_base = (unsigned)__cvta_generic_to_shared(smem);

    // load 32 W_hh rows (4 gates x 8 local hcols) into SMEM once
    for (int idx = tid; idx < 32 * 256; idx += 128) {
        int r  = idx >> 8;
        int c4 = (idx & 255) << 2;
        int g  = r >> 3, wl = r & 7;
        float4 v = *(const float4*)(Whh + (size_t)(g * Hdim + (bid << 3) + wl) * Hdim + c4);
        *(float4*)(sw + r * 1024 + c4) = v;
    }

    // zero this warp's slots of h buffer 0
    const int hslot = (hc0 >> 1) * 64 + lane * 2;   // hc0 even
    stcg_u64(&g_h2[0][hslot], 0ull);

    // per-warp W base: rows (g*8 + wi*2 + c), row stride 4096 B
    const unsigned swp0 = sw_base + (unsigned)((wi << 1) * 4096);

    // preload xw for t=0
    const float* xwp = g_xw + (size_t)lane * G4 + hc0;
    float2 xv[4];
#pragma unroll
    for (int g = 0; g < 4; g++) xv[g] = __ldg((const float2*)(xwp + g * 1024));

    float cs0 = 0.f, cs1 = 0.f;
    unsigned target = NBLK;
    grid_barrier(target);

    for (int t = 0; t < Tlen; t++) {
        const char* hr = (const char*)&g_h2[t & 1][0] + lane * 8;
        float*      hTw = &g_h2[(t + 1) & 1][0];

        unsigned long long a[4][2];
#pragma unroll
        for (int g = 0; g < 4; g++) {
            a[g][0] = pack2(xv[g].x, 0.f);
            a[g][1] = pack2(xv[g].y, 0.f);
        }

        // ---- k loop: 256 k4 (4 k each), no syncs, h straight from L2 ----
#pragma unroll 8
        for (int k4 = 0; k4 < 256; k4++) {
            unsigned long long h01 = ldcg_u64(hr + k4 * 512);
            unsigned long long h23 = ldcg_u64(hr + k4 * 512 + 256);
            const unsigned swk = swp0 + (unsigned)(k4 * 16);
            unsigned long long w01, w23;
            // gate 0 (rows 0..7 block), cols 0/1
            lds_v2u64(swk + 0 * 32768 + 0 * 4096, w01, w23);
            fma2(a[0][0], w01, h01); fma2(a[0][0], w23, h23);
            lds_v2u64(swk + 0 * 32768 + 1 * 4096, w01, w23);
            fma2(a[0][1], w01, h01); fma2(a[0][1], w23, h23);
            // gate 1
            lds_v2u64(swk + 1 * 32768 + 0 * 4096, w01, w23);
            fma2(a[1][0], w01, h01); fma2(a[1][0], w23, h23);
            lds_v2u64(swk + 1 * 32768 + 1 * 4096, w01, w23);
            fma2(a[1][1], w01, h01); fma2(a[1][1], w23, h23);
            // gate 2
            lds_v2u64(swk + 2 * 32768 + 0 * 4096, w01, w23);
            fma2(a[2][0], w01, h01); fma2(a[2][0], w23, h23);
            lds_v2u64(swk + 2 * 32768 + 1 * 4096, w01, w23);
            fma2(a[2][1], w01, h01); fma2(a[2][1], w23, h23);
            // gate 3
            lds_v2u64(swk + 3 * 32768 + 0 * 4096, w01, w23);
            fma2(a[3][0], w01, h01); fma2(a[3][0], w23, h23);
            lds_v2u64(swk + 3 * 32768 + 1 * 4096, w01, w23);
            fma2(a[3][1], w01, h01); fma2(a[3][1], w23, h23);
        }

        float lo, hi;
        unpack2(a[0][0], lo, hi); float zi0 = lo + hi;
        unpack2(a[1][0], lo, hi); float zf0 = lo + hi;
        unpack2(a[2][0], lo, hi); float zg0 = lo + hi;
        unpack2(a[3][0], lo, hi); float zo0 = lo + hi;
        unpack2(a[0][1], lo, hi); float zi1 = lo + hi;
        unpack2(a[1][1], lo, hi); float zf1 = lo + hi;
        unpack2(a[2][1], lo, hi); float zg1 = lo + hi;
        unpack2(a[3][1], lo, hi); float zo1 = lo + hi;

        cs0 = fmaf(sig_fast(zf0), cs0, sig_fast(zi0) * tanh_fast(zg0));
        cs1 = fmaf(sig_fast(zf1), cs1, sig_fast(zi1) * tanh_fast(zg1));
        float hv0 = sig_fast(zo0) * tanh_fast(cs0);
        float hv1 = sig_fast(zo1) * tanh_fast(cs1);

        stcg_u64(&hTw[hslot], pack2(hv0, hv1));
        float2 ov; ov.x = hv0; ov.y = hv1;
        *(float2*)&out[(size_t)lane * (Tlen * Hdim) + (size_t)t * Hdim + hc0] = ov;

        // prefetch next step's input projection (overlaps barrier wait)
        if (t + 1 < Tlen) {
            const float* nx = xwp + (size_t)(t + 1) * (Bsz * G4);
#pragma unroll
            for (int g = 0; g < 4; g++) xv[g] = __ldg((const float2*)(nx + g * 1024));
        }

        target += NBLK;
        grid_barrier(target);
    }
}

// =======================================================================
extern "C" void kernel_launch(void* const* d_in, const int* in_sizes, int n_in,
                              void* d_out, int out_size)
{
    const float* x    = (const float*)d_in[0];
    const float* Wih  = (const float*)d_in[1];
    const float* Whh  = (const float*)d_in[2];
    const float* bias = (const float*)d_in[3];
    float* out = (float*)d_out;

    cudaFuncSetAttribute(lstm_rec_kernel,
                         cudaFuncAttributeMaxDynamicSharedMemorySize, SMEM_BYTES);

    dim3 gt(G4 / 32, Idim / 32);             // (128, 32)
    transpose_wih_kernel<<<gt, 256>>>(Wih);

    dim3 g1(G4 / 128, (Bsz * Tlen) / 128);   // (32, 128)
    gemm_xw_kernel<<<g1, 256>>>(x, bias);

    lstm_rec_kernel<<<NBLK, 128, SMEM_BYTES>>>(Whh, out);
}

// round 6
// speedup vs baseline: 2.3334x; 2.3334x over previous
#include <cuda_runtime.h>
#include <math.h>

#define Bsz  32
#define Tlen 512
#define Idim 1024
#define Hdim 1024
#define G4   4096
#define NBLK 128

// ---------------- device scratch ----------------
__device__ float g_xw[(size_t)Tlen * Bsz * G4];       // [t][b][4H]
__device__ float g_hA[2][2][128][32][4];              // [buf][mt][kt][lane][reg] A-fragment layout (tf32 bits)
__device__ unsigned int g_bar;

// ---------------- helpers ----------------
__device__ __forceinline__ void fma2(unsigned long long& acc,
                                     unsigned long long a, unsigned long long b)
{
    asm volatile("fma.rn.f32x2 %0, %1, %2, %0;" : "+l"(acc) : "l"(a), "l"(b));
}
__device__ __forceinline__ unsigned long long bcast2(float v)
{
    unsigned long long r;
    asm("mov.b64 %0, {%1, %1};" : "=l"(r) : "f"(v));
    return r;
}
__device__ __forceinline__ void unpack2(unsigned long long p, float& lo, float& hi)
{
    asm("mov.b64 {%0, %1}, %2;" : "=f"(lo), "=f"(hi) : "l"(p));
}
__device__ __forceinline__ void lds_v2u64(unsigned addr,
                                          unsigned long long& a, unsigned long long& b)
{
    asm volatile("ld.shared.v2.u64 {%0, %1}, [%2];" : "=l"(a), "=l"(b) : "r"(addr));
}
__device__ __forceinline__ unsigned f2tf32(float f)
{
    unsigned r;
    asm("cvt.rna.tf32.f32 %0, %1;" : "=r"(r) : "f"(f));
    return r;
}
__device__ __forceinline__ void mma_tf32(float* d, const unsigned* a, const unsigned* b)
{
    asm volatile(
        "mma.sync.aligned.m16n8k8.row.col.f32.tf32.tf32.f32 "
        "{%0,%1,%2,%3},{%4,%5,%6,%7},{%8,%9},{%0,%1,%2,%3};"
        : "+f"(d[0]), "+f"(d[1]), "+f"(d[2]), "+f"(d[3])
        : "r"(a[0]), "r"(a[1]), "r"(a[2]), "r"(a[3]), "r"(b[0]), "r"(b[1]));
}
__device__ __forceinline__ float sig_fast(float x)
{
    return __frcp_rn(1.f + __expf(-x));
}
__device__ __forceinline__ float tanh_fast(float x)
{
    return fmaf(2.f, __frcp_rn(1.f + __expf(-2.f * x)), -1.f);
}

// =======================================================================
// Phase 1 (identical to best run): g_xw = x @ Wih^T + b.
// 128x128 tile, BK=16, 256 threads, 8x8 microtile, f32x2, double-buffered.
// =======================================================================
#define P1_BK   16
#define P1_PITCH 132

__global__ void __launch_bounds__(256, 2) gemm_xw_kernel(
    const float* __restrict__ x, const float* __restrict__ Wih,
    const float* __restrict__ bias)
{
    __shared__ float As[2][P1_BK][P1_PITCH];
    __shared__ float Bs[2][P1_BK][P1_PITCH];

    if (blockIdx.x == 0 && blockIdx.y == 0 && threadIdx.x == 0) g_bar = 0u;

    const int tid = threadIdx.x;
    const int bn  = blockIdx.x * 128;
    const int bm  = blockIdx.y * 128;
    const int tx8 = (tid & 15) << 3;
    const int ty8 = (tid >> 4) << 3;
    const int srow = tid >> 1;
    const int skq  = (tid & 1) << 3;
    const float* Ag = x   + (size_t)(bm + srow) * Idim + skq;
    const float* Bg = Wih + (size_t)(bn + srow) * Idim + skq;

    const unsigned bsb = (unsigned)__cvta_generic_to_shared(&Bs[0][0][0]);

    float4 ra0 = *(const float4*)(Ag + 0);
    float4 ra1 = *(const float4*)(Ag + 4);
    float4 rb0 = *(const float4*)(Bg + 0);
    float4 rb1 = *(const float4*)(Bg + 4);

    unsigned long long acc[8][4];
#pragma unroll
    for (int i = 0; i < 8; i++)
#pragma unroll
        for (int j = 0; j < 4; j++) acc[i][j] = 0ull;

    {
        float va[8] = {ra0.x, ra0.y, ra0.z, ra0.w, ra1.x, ra1.y, ra1.z, ra1.w};
        float vb[8] = {rb0.x, rb0.y, rb0.z, rb0.w, rb1.x, rb1.y, rb1.z, rb1.w};
#pragma unroll
        for (int j = 0; j < 8; j++) {
            As[0][skq + j][srow] = va[j];
            Bs[0][skq + j][srow] = vb[j];
        }
    }
    __syncthreads();

    int p = 0;
    for (int kt = 0; kt < Idim / P1_BK; kt++) {
        if (kt + 1 < Idim / P1_BK) {
            const float* ag = Ag + (kt + 1) * P1_BK;
            const float* bg = Bg + (kt + 1) * P1_BK;
            ra0 = *(const float4*)(ag + 0);
            ra1 = *(const float4*)(ag + 4);
            rb0 = *(const float4*)(bg + 0);
            rb1 = *(const float4*)(bg + 4);
        }

#pragma unroll
        for (int k = 0; k < P1_BK; k++) {
            float4 a0 = *(const float4*)&As[p][k][ty8];
            float4 a1 = *(const float4*)&As[p][k][ty8 + 4];
            unsigned baddr = bsb + (unsigned)(((p * P1_BK + k) * P1_PITCH + tx8) * 4);
            unsigned long long b0, b1, b2, b3;
            lds_v2u64(baddr,      b0, b1);
            lds_v2u64(baddr + 16, b2, b3);
            float av[8] = {a0.x, a0.y, a0.z, a0.w, a1.x, a1.y, a1.z, a1.w};
#pragma unroll
            for (int i = 0; i < 8; i++) {
                unsigned long long aa = bcast2(av[i]);
                fma2(acc[i][0], aa, b0);
                fma2(acc[i][1], aa, b1);
                fma2(acc[i][2], aa, b2);
                fma2(acc[i][3], aa, b3);
            }
        }

        if (kt + 1 < Idim / P1_BK) {
            __syncthreads();
            float va[8] = {ra0.x, ra0.y, ra0.z, ra0.w, ra1.x, ra1.y, ra1.z, ra1.w};
            float vb[8] = {rb0.x, rb0.y, rb0.z, rb0.w, rb1.x, rb1.y, rb1.z, rb1.w};
            int q = p ^ 1;
#pragma unroll
            for (int j = 0; j < 8; j++) {
                As[q][skq + j][srow] = va[j];
                Bs[q][skq + j][srow] = vb[j];
            }
            __syncthreads();
            p = q;
        }
    }

    float4 bb0 = *(const float4*)&bias[bn + tx8];
    float4 bb1 = *(const float4*)&bias[bn + tx8 + 4];
#pragma unroll
    for (int i = 0; i < 8; i++) {
        int m = bm + ty8 + i;
        int t = m & (Tlen - 1);
        int b = m >> 9;
        float4 o0, o1;
        unpack2(acc[i][0], o0.x, o0.y);
        unpack2(acc[i][1], o0.z, o0.w);
        unpack2(acc[i][2], o1.x, o1.y);
        unpack2(acc[i][3], o1.z, o1.w);
        o0.x += bb0.x; o0.y += bb0.y; o0.z += bb0.z; o0.w += bb0.w;
        o1.x += bb1.x; o1.y += bb1.y; o1.z += bb1.z; o1.w += bb1.w;
        float* dst = &g_xw[(size_t)t * (Bsz * G4) + (size_t)b * G4 + bn + tx8];
        *(float4*)(dst + 0) = o0;
        *(float4*)(dst + 4) = o1;
    }
}

// =======================================================================
// Phase 2: persistent tensor-core recurrence. 128 blocks x 256 threads.
// Block bid owns h-cols [bid*8, bid*8+8) x 4 gates = 4 n-tiles of 8.
// mma.sync m16n8k8 tf32; W fragments resident in SMEM (128KB, tf32);
// h exchanged via global in A-fragment layout (LDG.128 per fragment).
// Warp wi handles kt in [wi*16, wi*16+16); k-reduction through SMEM.
// =======================================================================
#define SWB_FLOATS (4 * 128 * 32 * 2)           // 32768 (128 KB)
#define SPART_FLOATS (8 * 2 * 4 * 32 * 4)       // 4096  (16 KB)
#define SMEM_P2 ((SWB_FLOATS + SPART_FLOATS) * 4)

__device__ __forceinline__ void grid_barrier(unsigned target)
{
    __syncthreads();
    if (threadIdx.x == 0) {
        __threadfence();
        asm volatile("red.release.gpu.global.add.u32 [%0], %1;"
                     :: "l"(&g_bar), "r"(1u) : "memory");
        unsigned v;
        do {
            asm volatile("ld.acquire.gpu.global.u32 %0, [%1];"
                         : "=r"(v) : "l"(&g_bar) : "memory");
        } while (v < target);
    }
    __syncthreads();
}

__global__ void __launch_bounds__(256, 1) lstm_rec_kernel(
    const float* __restrict__ Whh, float* __restrict__ out)
{
    extern __shared__ float smem[];
    float* sWB   = smem;                 // [g][kt][lane][2] tf32 B fragments
    float* sPart = smem + SWB_FLOATS;    // [wi][mt][g][lane][4] fp32 partial D

    const int tid  = threadIdx.x;
    const int bid  = blockIdx.x;
    const int wi   = tid >> 5;
    const int lane = tid & 31;

    // ---- build W B-fragments in SMEM (once), tf32 ----
    for (int idx = tid; idx < 4 * 128 * 32; idx += 256) {
        int l  = idx & 31;
        int kt = (idx >> 5) & 127;
        int g  = idx >> 12;
        int row = g * 1024 + bid * 8 + (l >> 2);
        int k0  = kt * 8 + (l & 3);
        unsigned* dst = (unsigned*)&sWB[((g * 128 + kt) * 32 + l) * 2];
        dst[0] = f2tf32(Whh[(size_t)row * Hdim + k0]);
        dst[1] = f2tf32(Whh[(size_t)row * Hdim + k0 + 4]);
    }

    // ---- reducer/producer identity: thread owns (batch rb, local hcol rh) ----
    const int rb = tid >> 3;            // 0..31
    const int rh = tid & 7;             // 0..7
    const int j  = bid * 8 + rh;        // global h index

    // A-fragment slot of h[rb][j]
    const int p_mt   = rb >> 4;
    const int p_kt   = j >> 3;
    const int p_lane = (rb & 7) * 4 + (rh & 3);
    const int p_reg  = ((rb & 15) >> 3) + 2 * (rh >> 2);

    g_hA[0][p_mt][p_kt][p_lane][p_reg] = 0.f;   // zero init (tf32 0 == 0)

    // D-fragment slot for readback
    const int laneD = (rb & 7) * 4 + (rh >> 1);
    const int regD  = (rh & 1) + 2 * ((rb & 15) >> 3);
    const int mtD   = rb >> 4;

    const float* xwp = g_xw + (size_t)rb * G4 + j;
    float xv[4];
#pragma unroll
    for (int g = 0; g < 4; g++) xv[g] = __ldg(xwp + g * 1024);

    float c_state = 0.f;
    unsigned target = NBLK;
    grid_barrier(target);

    const int kt0 = wi * 16;

    for (int t = 0; t < Tlen; t++) {
        const int rbuf = t & 1, wbuf = rbuf ^ 1;

        // ---- MMA: D[mt][g] += A(h) x B(W) over 16 k-tiles ----
        float D[2][4][4];
#pragma unroll
        for (int m = 0; m < 2; m++)
#pragma unroll
            for (int n = 0; n < 4; n++)
#pragma unroll
                for (int q = 0; q < 4; q++) D[m][n][q] = 0.f;

        uint4 A0 = __ldcg((const uint4*)&g_hA[rbuf][0][kt0][lane][0]);
        uint4 A1 = __ldcg((const uint4*)&g_hA[rbuf][1][kt0][lane][0]);
#pragma unroll
        for (int i = 0; i < 16; i++) {
            uint4 a0 = A0, a1 = A1;
            if (i < 15) {
                A0 = __ldcg((const uint4*)&g_hA[rbuf][0][kt0 + i + 1][lane][0]);
                A1 = __ldcg((const uint4*)&g_hA[rbuf][1][kt0 + i + 1][lane][0]);
            }
#pragma unroll
            for (int g = 0; g < 4; g++) {
                unsigned bfrag[2];
                *(uint2*)bfrag = *(const uint2*)&sWB[((g * 128 + kt0 + i) * 32 + lane) * 2];
                mma_tf32(D[0][g], (const unsigned*)&a0, bfrag);
                mma_tf32(D[1][g], (const unsigned*)&a1, bfrag);
            }
        }

        // ---- write partial D to SMEM ----
#pragma unroll
        for (int m = 0; m < 2; m++)
#pragma unroll
            for (int g = 0; g < 4; g++)
                *(float4*)&sPart[(((wi * 2 + m) * 4 + g) * 32 + lane) * 4] =
                    *(float4*)D[m][g];
        __syncthreads();

        // ---- reduce across 8 warps + gates ----
        float z[4];
#pragma unroll
        for (int g = 0; g < 4; g++) {
            float s = xv[g];
#pragma unroll
            for (int w = 0; w < 8; w++)
                s += sPart[(((w * 2 + mtD) * 4 + g) * 32 + laneD) * 4 + regD];
            z[g] = s;
        }

        float ig = sig_fast(z[0]);
        float fg = sig_fast(z[1]);
        float gg = tanh_fast(z[2]);
        float og = sig_fast(z[3]);
        c_state = fmaf(fg, c_state, ig * gg);
        float hv = og * tanh_fast(c_state);

        // publish h (tf32 bits) into A-fragment layout; fp32 to out
        *(unsigned*)&g_hA[wbuf][p_mt][p_kt][p_lane][p_reg] = f2tf32(hv);
        out[((size_t)rb * Tlen + t) * Hdim + j] = hv;

        if (t + 1 < Tlen) {
            const float* nx = xwp + (size_t)(t + 1) * (Bsz * G4);
#pragma unroll
            for (int g = 0; g < 4; g++) xv[g] = __ldg(nx + g * 1024);
        }

        target += NBLK;
        grid_barrier(target);
    }
}

// =======================================================================
extern "C" void kernel_launch(void* const* d_in, const int* in_sizes, int n_in,
                              void* d_out, int out_size)
{
    const float* x    = (const float*)d_in[0];
    const float* Wih  = (const float*)d_in[1];
    const float* Whh  = (const float*)d_in[2];
    const float* bias = (const float*)d_in[3];
    float* out = (float*)d_out;

    cudaFuncSetAttribute(lstm_rec_kernel,
                         cudaFuncAttributeMaxDynamicSharedMemorySize, SMEM_P2);

    dim3 g1(G4 / 128, (Bsz * Tlen) / 128);   // (32, 128)
    gemm_xw_kernel<<<g1, 256>>>(x, Wih, bias);

    lstm_rec_kernel<<<NBLK, 256, SMEM_P2>>>(Whh, out);
}

// round 7
// speedup vs baseline: 2.7639x; 1.1845x over previous
#include <cuda_runtime.h>
#include <math.h>

#define Bsz  32
#define Tlen 512
#define Idim 1024
#define Hdim 1024
#define G4   4096
#define NBLK 128

// ---------------- device scratch ----------------
__device__ float g_xw[(size_t)Tlen * Bsz * G4];       // [t][b][4H]
__device__ float g_hA[2][2][128][32][4];              // [buf][mt][kt][lane][reg] A-frag (tf32 bits)
__device__ unsigned int g_bar;

// ---------------- helpers ----------------
__device__ __forceinline__ unsigned f2tf32(float f)
{
    unsigned r;
    asm("cvt.rna.tf32.f32 %0, %1;" : "=r"(r) : "f"(f));
    return r;
}
__device__ __forceinline__ void mma_tf32(float* d, const unsigned* a, const unsigned* b)
{
    asm volatile(
        "mma.sync.aligned.m16n8k8.row.col.f32.tf32.tf32.f32 "
        "{%0,%1,%2,%3},{%4,%5,%6,%7},{%8,%9},{%0,%1,%2,%3};"
        : "+f"(d[0]), "+f"(d[1]), "+f"(d[2]), "+f"(d[3])
        : "r"(a[0]), "r"(a[1]), "r"(a[2]), "r"(a[3]), "r"(b[0]), "r"(b[1]));
}
__device__ __forceinline__ void cp_async16(unsigned dst, const void* src)
{
    asm volatile("cp.async.cg.shared.global [%0], [%1], 16;" :: "r"(dst), "l"(src));
}
#define CP_COMMIT()  asm volatile("cp.async.commit_group;")
#define CP_WAIT(N)   asm volatile("cp.async.wait_group %0;" :: "n"(N))

__device__ __forceinline__ float sig_fast(float x)
{
    return __frcp_rn(1.f + __expf(-x));
}
__device__ __forceinline__ float tanh_fast(float x)
{
    return fmaf(2.f, __frcp_rn(1.f + __expf(-2.f * x)), -1.f);
}
// split a into tf32 hi + tf32 lo (3xTF32 scheme)
__device__ __forceinline__ void split_tf32(float a, unsigned& hi, unsigned& lo)
{
    hi = f2tf32(a);
    float hf = __uint_as_float(hi);      // tf32 bits are a valid fp32 value
    lo = f2tf32(a - hf);
}

// =======================================================================
// Phase 1: g_xw = x @ Wih^T + b via tf32x3 mma.sync.
// CTA 128x128, BK=32, 256 thr (8 warps, 2Mx4N), warp tile 64x32.
// smem: A[2][128][36], B[2][128][36] (fp32), cp.async double buffered.
// =======================================================================
#define P1_PAD   36
#define P1_BUF   (128 * P1_PAD)                 // floats per buffer
#define P1_SMEM  (4 * P1_BUF * 4)               // bytes: A(2) + B(2)

__global__ void __launch_bounds__(256, 1) gemm_xw_kernel(
    const float* __restrict__ x, const float* __restrict__ Wih,
    const float* __restrict__ bias)
{
    extern __shared__ float sm[];
    float* Abuf = sm;                   // [2][128][36]
    float* Bbuf = sm + 2 * P1_BUF;      // [2][128][36]

    if (blockIdx.x == 0 && blockIdx.y == 0 && threadIdx.x == 0) g_bar = 0u;

    const int tid  = threadIdx.x;
    const int wi   = tid >> 5;
    const int lane = tid & 31;
    const int wm   = wi >> 2;            // 0..1
    const int wn   = wi & 3;             // 0..3
    const int g    = lane >> 2;          // fragment group row
    const int tg   = lane & 3;           // fragment thread-in-group

    const int bn = blockIdx.x * 128;
    const int bm = blockIdx.y * 128;

    const unsigned a_smb = (unsigned)__cvta_generic_to_shared(Abuf);
    const unsigned b_smb = (unsigned)__cvta_generic_to_shared(Bbuf);

    // staging: idx = tid + p*256 (p 0..3): row = idx>>3, seg = idx&7
    const int srow = tid >> 3;
    const int sseg = tid & 7;

    // ---- prologue: chunk 0 ----
#pragma unroll
    for (int p = 0; p < 4; p++) {
        int row = srow + p * 32;
        unsigned doff = (unsigned)((row * P1_PAD + sseg * 4) * 4);
        cp_async16(a_smb + doff, x   + (size_t)(bm + row) * Idim + sseg * 4);
        cp_async16(b_smb + doff, Wih + (size_t)(bn + row) * Idim + sseg * 4);
    }
    CP_COMMIT();

    float D[4][4][4];
#pragma unroll
    for (int mi = 0; mi < 4; mi++)
#pragma unroll
        for (int ni = 0; ni < 4; ni++)
#pragma unroll
            for (int q = 0; q < 4; q++) D[mi][ni][q] = 0.f;

    for (int kc = 0; kc < 32; kc++) {
        const int buf = kc & 1;
        if (kc + 1 < 32) {
            const int nb = (kc + 1) & 1;
            const int k0 = (kc + 1) * 32;
#pragma unroll
            for (int p = 0; p < 4; p++) {
                int row = srow + p * 32;
                unsigned doff = (unsigned)((nb * P1_BUF + row * P1_PAD + sseg * 4) * 4);
                cp_async16(a_smb + doff, x   + (size_t)(bm + row) * Idim + k0 + sseg * 4);
                cp_async16(b_smb + doff, Wih + (size_t)(bn + row) * Idim + k0 + sseg * 4);
            }
            CP_COMMIT();
            CP_WAIT(1);
        } else {
            CP_WAIT(0);
        }
        __syncthreads();

        const float* Ab = Abuf + buf * P1_BUF;
        const float* Bb = Bbuf + buf * P1_BUF;

#pragma unroll
        for (int k8 = 0; k8 < 4; k8++) {
            const int kc0 = k8 * 8;
            unsigned Ahi[4][4], Alo[4][4], Bhi[4][2], Blo[4][2];
#pragma unroll
            for (int mi = 0; mi < 4; mi++) {
                const float* ap = Ab + (wm * 64 + mi * 16 + g) * P1_PAD + kc0 + tg;
                float a0 = ap[0];
                float a1 = ap[8 * P1_PAD];
                float a2 = ap[4];
                float a3 = ap[8 * P1_PAD + 4];
                split_tf32(a0, Ahi[mi][0], Alo[mi][0]);
                split_tf32(a1, Ahi[mi][1], Alo[mi][1]);
                split_tf32(a2, Ahi[mi][2], Alo[mi][2]);
                split_tf32(a3, Ahi[mi][3], Alo[mi][3]);
            }
#pragma unroll
            for (int ni = 0; ni < 4; ni++) {
                const float* bp = Bb + (wn * 32 + ni * 8 + g) * P1_PAD + kc0 + tg;
                float b0 = bp[0];
                float b1 = bp[4];
                split_tf32(b0, Bhi[ni][0], Blo[ni][0]);
                split_tf32(b1, Bhi[ni][1], Blo[ni][1]);
            }
#pragma unroll
            for (int mi = 0; mi < 4; mi++)
#pragma unroll
                for (int ni = 0; ni < 4; ni++) {
                    mma_tf32(D[mi][ni], Ahi[mi], Bhi[ni]);
                    mma_tf32(D[mi][ni], Alo[mi], Bhi[ni]);
                    mma_tf32(D[mi][ni], Ahi[mi], Blo[ni]);
                }
        }
        __syncthreads();   // done reading buf before it is overwritten
    }

    // ---- epilogue: +bias, scatter to g_xw[t][b][n] ----
    float2 bv[4];
#pragma unroll
    for (int ni = 0; ni < 4; ni++) {
        int j0 = bn + wn * 32 + ni * 8 + tg * 2;
        bv[ni].x = __ldg(bias + j0);
        bv[ni].y = __ldg(bias + j0 + 1);
    }
#pragma unroll
    for (int mi = 0; mi < 4; mi++) {
        int r0 = bm + wm * 64 + mi * 16 + g;
        int r1 = r0 + 8;
        int t0 = r0 & (Tlen - 1), b0 = r0 >> 9;
        int t1 = r1 & (Tlen - 1), b1 = r1 >> 9;
        float* base0 = &g_xw[(size_t)t0 * (Bsz * G4) + (size_t)b0 * G4];
        float* base1 = &g_xw[(size_t)t1 * (Bsz * G4) + (size_t)b1 * G4];
#pragma unroll
        for (int ni = 0; ni < 4; ni++) {
            int j0 = bn + wn * 32 + ni * 8 + tg * 2;
            float2 v0; v0.x = D[mi][ni][0] + bv[ni].x; v0.y = D[mi][ni][1] + bv[ni].y;
            float2 v1; v1.x = D[mi][ni][2] + bv[ni].x; v1.y = D[mi][ni][3] + bv[ni].y;
            *(float2*)(base0 + j0) = v0;
            *(float2*)(base1 + j0) = v1;
        }
    }
}

// =======================================================================
// Phase 2: persistent tensor-core recurrence (UNCHANGED from best run).
// =======================================================================
#define SWB_FLOATS (4 * 128 * 32 * 2)           // 32768 (128 KB)
#define SPART_FLOATS (8 * 2 * 4 * 32 * 4)       // 4096  (16 KB)
#define SMEM_P2 ((SWB_FLOATS + SPART_FLOATS) * 4)

__device__ __forceinline__ void grid_barrier(unsigned target)
{
    __syncthreads();
    if (threadIdx.x == 0) {
        __threadfence();
        asm volatile("red.release.gpu.global.add.u32 [%0], %1;"
                     :: "l"(&g_bar), "r"(1u) : "memory");
        unsigned v;
        do {
            asm volatile("ld.acquire.gpu.global.u32 %0, [%1];"
                         : "=r"(v) : "l"(&g_bar) : "memory");
        } while (v < target);
    }
    __syncthreads();
}

__global__ void __launch_bounds__(256, 1) lstm_rec_kernel(
    const float* __restrict__ Whh, float* __restrict__ out)
{
    extern __shared__ float smem[];
    float* sWB   = smem;                 // [g][kt][lane][2] tf32 B fragments
    float* sPart = smem + SWB_FLOATS;    // [wi][mt][g][lane][4] fp32 partial D

    const int tid  = threadIdx.x;
    const int bid  = blockIdx.x;
    const int wi   = tid >> 5;
    const int lane = tid & 31;

    // ---- build W B-fragments in SMEM (once), tf32 ----
    for (int idx = tid; idx < 4 * 128 * 32; idx += 256) {
        int l  = idx & 31;
        int kt = (idx >> 5) & 127;
        int g  = idx >> 12;
        int row = g * 1024 + bid * 8 + (l >> 2);
        int k0  = kt * 8 + (l & 3);
        unsigned* dst = (unsigned*)&sWB[((g * 128 + kt) * 32 + l) * 2];
        dst[0] = f2tf32(Whh[(size_t)row * Hdim + k0]);
        dst[1] = f2tf32(Whh[(size_t)row * Hdim + k0 + 4]);
    }

    const int rb = tid >> 3;            // batch
    const int rh = tid & 7;             // local h col
    const int j  = bid * 8 + rh;

    const int p_mt   = rb >> 4;
    const int p_kt   = j >> 3;
    const int p_lane = (rb & 7) * 4 + (rh & 3);
    const int p_reg  = ((rb & 15) >> 3) + 2 * (rh >> 2);

    g_hA[0][p_mt][p_kt][p_lane][p_reg] = 0.f;

    const int laneD = (rb & 7) * 4 + (rh >> 1);
    const int regD  = (rh & 1) + 2 * ((rb & 15) >> 3);
    const int mtD   = rb >> 4;

    const float* xwp = g_xw + (size_t)rb * G4 + j;
    float xv[4];
#pragma unroll
    for (int g = 0; g < 4; g++) xv[g] = __ldg(xwp + g * 1024);

    float c_state = 0.f;
    unsigned target = NBLK;
    grid_barrier(target);

    const int kt0 = wi * 16;

    for (int t = 0; t < Tlen; t++) {
        const int rbuf = t & 1, wbuf = rbuf ^ 1;

        float D[2][4][4];
#pragma unroll
        for (int m = 0; m < 2; m++)
#pragma unroll
            for (int n = 0; n < 4; n++)
#pragma unroll
                for (int q = 0; q < 4; q++) D[m][n][q] = 0.f;

        uint4 A0 = __ldcg((const uint4*)&g_hA[rbuf][0][kt0][lane][0]);
        uint4 A1 = __ldcg((const uint4*)&g_hA[rbuf][1][kt0][lane][0]);
#pragma unroll
        for (int i = 0; i < 16; i++) {
            uint4 a0 = A0, a1 = A1;
            if (i < 15) {
                A0 = __ldcg((const uint4*)&g_hA[rbuf][0][kt0 + i + 1][lane][0]);
                A1 = __ldcg((const uint4*)&g_hA[rbuf][1][kt0 + i + 1][lane][0]);
            }
#pragma unroll
            for (int g = 0; g < 4; g++) {
                unsigned bfrag[2];
                *(uint2*)bfrag = *(const uint2*)&sWB[((g * 128 + kt0 + i) * 32 + lane) * 2];
                mma_tf32(D[0][g], (const unsigned*)&a0, bfrag);
                mma_tf32(D[1][g], (const unsigned*)&a1, bfrag);
            }
        }

#pragma unroll
        for (int m = 0; m < 2; m++)
#pragma unroll
            for (int g = 0; g < 4; g++)
                *(float4*)&sPart[(((wi * 2 + m) * 4 + g) * 32 + lane) * 4] =
                    *(float4*)D[m][g];
        __syncthreads();

        float z[4];
#pragma unroll
        for (int g = 0; g < 4; g++) {
            float s = xv[g];
#pragma unroll
            for (int w = 0; w < 8; w++)
                s += sPart[(((w * 2 + mtD) * 4 + g) * 32 + laneD) * 4 + regD];
            z[g] = s;
        }

        float ig = sig_fast(z[0]);
        float fg = sig_fast(z[1]);
        float gg = tanh_fast(z[2]);
        float og = sig_fast(z[3]);
        c_state = fmaf(fg, c_state, ig * gg);
        float hv = og * tanh_fast(c_state);

        *(unsigned*)&g_hA[wbuf][p_mt][p_kt][p_lane][p_reg] = f2tf32(hv);
        out[((size_t)rb * Tlen + t) * Hdim + j] = hv;

        if (t + 1 < Tlen) {
            const float* nx = xwp + (size_t)(t + 1) * (Bsz * G4);
#pragma unroll
            for (int g = 0; g < 4; g++) xv[g] = __ldg(nx + g * 1024);
        }

        target += NBLK;
        grid_barrier(target);
    }
}

// =======================================================================
extern "C" void kernel_launch(void* const* d_in, const int* in_sizes, int n_in,
                              void* d_out, int out_size)
{
    const float* x    = (const float*)d_in[0];
    const float* Wih  = (const float*)d_in[1];
    const float* Whh  = (const float*)d_in[2];
    const float* bias = (const float*)d_in[3];
    float* out = (float*)d_out;

    cudaFuncSetAttribute(gemm_xw_kernel,
                         cudaFuncAttributeMaxDynamicSharedMemorySize, P1_SMEM);
    cudaFuncSetAttribute(lstm_rec_kernel,
                         cudaFuncAttributeMaxDynamicSharedMemorySize, SMEM_P2);

    dim3 g1(G4 / 128, (Bsz * Tlen) / 128);   // (32, 128)
    gemm_xw_kernel<<<g1, 256, P1_SMEM>>>(x, Wih, bias);

    lstm_rec_kernel<<<NBLK, 256, SMEM_P2>>>(Whh, out);
}

// round 8
// speedup vs baseline: 3.8458x; 1.3914x over previous
#include <cuda_runtime.h>
#include <math.h>

#define Bsz  32
#define Tlen 512
#define Idim 1024
#define Hdim 1024
#define G4   4096
#define NBLK 128

// ---------------- device scratch ----------------
__device__ float g_xw[(size_t)Tlen * Bsz * G4];       // [t][b][4H]
__device__ float g_hA[2][2][128][32][4];              // [buf][mt][kt][lane][reg] A-frag (tf32 bits)
__device__ unsigned int g_bar;

// ---------------- helpers ----------------
__device__ __forceinline__ unsigned f2tf32(float f)
{
    unsigned r;
    asm("cvt.rna.tf32.f32 %0, %1;" : "=r"(r) : "f"(f));
    return r;
}
__device__ __forceinline__ void mma_tf32(float* d, const unsigned* a, const unsigned* b)
{
    asm volatile(
        "mma.sync.aligned.m16n8k8.row.col.f32.tf32.tf32.f32 "
        "{%0,%1,%2,%3},{%4,%5,%6,%7},{%8,%9},{%0,%1,%2,%3};"
        : "+f"(d[0]), "+f"(d[1]), "+f"(d[2]), "+f"(d[3])
        : "r"(a[0]), "r"(a[1]), "r"(a[2]), "r"(a[3]), "r"(b[0]), "r"(b[1]));
}
__device__ __forceinline__ void cp_async16(unsigned dst, const void* src)
{
    asm volatile("cp.async.cg.shared.global [%0], [%1], 16;" :: "r"(dst), "l"(src));
}
#define CP_COMMIT()  asm volatile("cp.async.commit_group;")
#define CP_WAIT(N)   asm volatile("cp.async.wait_group %0;" :: "n"(N))

__device__ __forceinline__ float sig_fast(float x)
{
    return __frcp_rn(1.f + __expf(-x));
}
__device__ __forceinline__ float tanh_fast(float x)
{
    return fmaf(2.f, __frcp_rn(1.f + __expf(-2.f * x)), -1.f);
}

// =======================================================================
// Phase 1: g_xw = x @ Wih^T + b via tf32x1 mma.sync (raw fp32 bits as
// tf32 operands — HW reads the tf32 mantissa subset; no cvt in the loop).
// CTA 128x128, BK=32, 256 thr (8 warps, 2Mx4N), warp tile 64x32.
// =======================================================================
#define P1_PAD   36
#define P1_BUF   (128 * P1_PAD)
#define P1_SMEM  (4 * P1_BUF * 4)

__global__ void __launch_bounds__(256, 1) gemm_xw_kernel(
    const float* __restrict__ x, const float* __restrict__ Wih,
    const float* __restrict__ bias)
{
    extern __shared__ float sm[];
    float* Abuf = sm;                   // [2][128][36]
    float* Bbuf = sm + 2 * P1_BUF;      // [2][128][36]

    if (blockIdx.x == 0 && blockIdx.y == 0 && threadIdx.x == 0) g_bar = 0u;

    const int tid  = threadIdx.x;
    const int wi   = tid >> 5;
    const int lane = tid & 31;
    const int wm   = wi >> 2;            // 0..1
    const int wn   = wi & 3;             // 0..3
    const int g    = lane >> 2;
    const int tg   = lane & 3;

    const int bn = blockIdx.x * 128;
    const int bm = blockIdx.y * 128;

    const unsigned a_smb = (unsigned)__cvta_generic_to_shared(Abuf);
    const unsigned b_smb = (unsigned)__cvta_generic_to_shared(Bbuf);

    const int srow = tid >> 3;
    const int sseg = tid & 7;

#pragma unroll
    for (int p = 0; p < 4; p++) {
        int row = srow + p * 32;
        unsigned doff = (unsigned)((row * P1_PAD + sseg * 4) * 4);
        cp_async16(a_smb + doff, x   + (size_t)(bm + row) * Idim + sseg * 4);
        cp_async16(b_smb + doff, Wih + (size_t)(bn + row) * Idim + sseg * 4);
    }
    CP_COMMIT();

    float D[4][4][4];
#pragma unroll
    for (int mi = 0; mi < 4; mi++)
#pragma unroll
        for (int ni = 0; ni < 4; ni++)
#pragma unroll
            for (int q = 0; q < 4; q++) D[mi][ni][q] = 0.f;

    for (int kc = 0; kc < 32; kc++) {
        const int buf = kc & 1;
        if (kc + 1 < 32) {
            const int nb = (kc + 1) & 1;
            const int k0 = (kc + 1) * 32;
#pragma unroll
            for (int p = 0; p < 4; p++) {
                int row = srow + p * 32;
                unsigned doff = (unsigned)((nb * P1_BUF + row * P1_PAD + sseg * 4) * 4);
                cp_async16(a_smb + doff, x   + (size_t)(bm + row) * Idim + k0 + sseg * 4);
                cp_async16(b_smb + doff, Wih + (size_t)(bn + row) * Idim + k0 + sseg * 4);
            }
            CP_COMMIT();
            CP_WAIT(1);
        } else {
            CP_WAIT(0);
        }
        __syncthreads();

        const unsigned* Ab = (const unsigned*)(Abuf + buf * P1_BUF);
        const unsigned* Bb = (const unsigned*)(Bbuf + buf * P1_BUF);

#pragma unroll
        for (int k8 = 0; k8 < 4; k8++) {
            const int kc0 = k8 * 8;
            unsigned A[4][4], Bf[4][2];
#pragma unroll
            for (int mi = 0; mi < 4; mi++) {
                const unsigned* ap = Ab + (wm * 64 + mi * 16 + g) * P1_PAD + kc0 + tg;
                A[mi][0] = ap[0];
                A[mi][1] = ap[8 * P1_PAD];
                A[mi][2] = ap[4];
                A[mi][3] = ap[8 * P1_PAD + 4];
            }
#pragma unroll
            for (int ni = 0; ni < 4; ni++) {
                const unsigned* bp = Bb + (wn * 32 + ni * 8 + g) * P1_PAD + kc0 + tg;
                Bf[ni][0] = bp[0];
                Bf[ni][1] = bp[4];
            }
#pragma unroll
            for (int mi = 0; mi < 4; mi++)
#pragma unroll
                for (int ni = 0; ni < 4; ni++)
                    mma_tf32(D[mi][ni], A[mi], Bf[ni]);
        }
        __syncthreads();
    }

    // ---- epilogue: +bias, scatter to g_xw[t][b][n] ----
    float2 bv[4];
#pragma unroll
    for (int ni = 0; ni < 4; ni++) {
        int j0 = bn + wn * 32 + ni * 8 + tg * 2;
        bv[ni].x = __ldg(bias + j0);
        bv[ni].y = __ldg(bias + j0 + 1);
    }
#pragma unroll
    for (int mi = 0; mi < 4; mi++) {
        int r0 = bm + wm * 64 + mi * 16 + g;
        int r1 = r0 + 8;
        int t0 = r0 & (Tlen - 1), b0 = r0 >> 9;
        int t1 = r1 & (Tlen - 1), b1 = r1 >> 9;
        float* base0 = &g_xw[(size_t)t0 * (Bsz * G4) + (size_t)b0 * G4];
        float* base1 = &g_xw[(size_t)t1 * (Bsz * G4) + (size_t)b1 * G4];
#pragma unroll
        for (int ni = 0; ni < 4; ni++) {
            int j0 = bn + wn * 32 + ni * 8 + tg * 2;
            float2 v0; v0.x = D[mi][ni][0] + bv[ni].x; v0.y = D[mi][ni][1] + bv[ni].y;
            float2 v1; v1.x = D[mi][ni][2] + bv[ni].x; v1.y = D[mi][ni][3] + bv[ni].y;
            *(float2*)(base0 + j0) = v0;
            *(float2*)(base1 + j0) = v1;
        }
    }
}

// =======================================================================
// Phase 2: persistent tensor-core recurrence (UNCHANGED from best run).
// =======================================================================
#define SWB_FLOATS (4 * 128 * 32 * 2)           // 32768 (128 KB)
#define SPART_FLOATS (8 * 2 * 4 * 32 * 4)       // 4096  (16 KB)
#define SMEM_P2 ((SWB_FLOATS + SPART_FLOATS) * 4)

__device__ __forceinline__ void grid_barrier(unsigned target)
{
    __syncthreads();
    if (threadIdx.x == 0) {
        __threadfence();
        asm volatile("red.release.gpu.global.add.u32 [%0], %1;"
                     :: "l"(&g_bar), "r"(1u) : "memory");
        unsigned v;
        do {
            asm volatile("ld.acquire.gpu.global.u32 %0, [%1];"
                         : "=r"(v) : "l"(&g_bar) : "memory");
        } while (v < target);
    }
    __syncthreads();
}

__global__ void __launch_bounds__(256, 1) lstm_rec_kernel(
    const float* __restrict__ Whh, float* __restrict__ out)
{
    extern __shared__ float smem[];
    float* sWB   = smem;                 // [g][kt][lane][2] tf32 B fragments
    float* sPart = smem + SWB_FLOATS;    // [wi][mt][g][lane][4] fp32 partial D

    const int tid  = threadIdx.x;
    const int bid  = blockIdx.x;
    const int wi   = tid >> 5;
    const int lane = tid & 31;

    for (int idx = tid; idx < 4 * 128 * 32; idx += 256) {
        int l  = idx & 31;
        int kt = (idx >> 5) & 127;
        int g  = idx >> 12;
        int row = g * 1024 + bid * 8 + (l >> 2);
        int k0  = kt * 8 + (l & 3);
        unsigned* dst = (unsigned*)&sWB[((g * 128 + kt) * 32 + l) * 2];
        dst[0] = f2tf32(Whh[(size_t)row * Hdim + k0]);
        dst[1] = f2tf32(Whh[(size_t)row * Hdim + k0 + 4]);
    }

    const int rb = tid >> 3;
    const int rh = tid & 7;
    const int j  = bid * 8 + rh;

    const int p_mt   = rb >> 4;
    const int p_kt   = j >> 3;
    const int p_lane = (rb & 7) * 4 + (rh & 3);
    const int p_reg  = ((rb & 15) >> 3) + 2 * (rh >> 2);

    g_hA[0][p_mt][p_kt][p_lane][p_reg] = 0.f;

    const int laneD = (rb & 7) * 4 + (rh >> 1);
    const int regD  = (rh & 1) + 2 * ((rb & 15) >> 3);
    const int mtD   = rb >> 4;

    const float* xwp = g_xw + (size_t)rb * G4 + j;
    float xv[4];
#pragma unroll
    for (int g = 0; g < 4; g++) xv[g] = __ldg(xwp + g * 1024);

    float c_state = 0.f;
    unsigned target = NBLK;
    grid_barrier(target);

    const int kt0 = wi * 16;

    for (int t = 0; t < Tlen; t++) {
        const int rbuf = t & 1, wbuf = rbuf ^ 1;

        float D[2][4][4];
#pragma unroll
        for (int m = 0; m < 2; m++)
#pragma unroll
            for (int n = 0; n < 4; n++)
#pragma unroll
                for (int q = 0; q < 4; q++) D[m][n][q] = 0.f;

        uint4 A0 = __ldcg((const uint4*)&g_hA[rbuf][0][kt0][lane][0]);
        uint4 A1 = __ldcg((const uint4*)&g_hA[rbuf][1][kt0][lane][0]);
#pragma unroll
        for (int i = 0; i < 16; i++) {
            uint4 a0 = A0, a1 = A1;
            if (i < 15) {
                A0 = __ldcg((const uint4*)&g_hA[rbuf][0][kt0 + i + 1][lane][0]);
                A1 = __ldcg((const uint4*)&g_hA[rbuf][1][kt0 + i + 1][lane][0]);
            }
#pragma unroll
            for (int g = 0; g < 4; g++) {
                unsigned bfrag[2];
                *(uint2*)bfrag = *(const uint2*)&sWB[((g * 128 + kt0 + i) * 32 + lane) * 2];
                mma_tf32(D[0][g], (const unsigned*)&a0, bfrag);
                mma_tf32(D[1][g], (const unsigned*)&a1, bfrag);
            }
        }

#pragma unroll
        for (int m = 0; m < 2; m++)
#pragma unroll
            for (int g = 0; g < 4; g++)
                *(float4*)&sPart[(((wi * 2 + m) * 4 + g) * 32 + lane) * 4] =
                    *(float4*)D[m][g];
        __syncthreads();

        float z[4];
#pragma unroll
        for (int g = 0; g < 4; g++) {
            float s = xv[g];
#pragma unroll
            for (int w = 0; w < 8; w++)
                s += sPart[(((w * 2 + mtD) * 4 + g) * 32 + laneD) * 4 + regD];
            z[g] = s;
        }

        float ig = sig_fast(z[0]);
        float fg = sig_fast(z[1]);
        float gg = tanh_fast(z[2]);
        float og = sig_fast(z[3]);
        c_state = fmaf(fg, c_state, ig * gg);
        float hv = og * tanh_fast(c_state);

        *(unsigned*)&g_hA[wbuf][p_mt][p_kt][p_lane][p_reg] = f2tf32(hv);
        out[((size_t)rb * Tlen + t) * Hdim + j] = hv;

        if (t + 1 < Tlen) {
            const float* nx = xwp + (size_t)(t + 1) * (Bsz * G4);
#pragma unroll
            for (int g = 0; g < 4; g++) xv[g] = __ldg(nx + g * 1024);
        }

        target += NBLK;
        grid_barrier(target);
    }
}

// =======================================================================
extern "C" void kernel_launch(void* const* d_in, const int* in_sizes, int n_in,
                              void* d_out, int out_size)
{
    const float* x    = (const float*)d_in[0];
    const float* Wih  = (const float*)d_in[1];
    const float* Whh  = (const float*)d_in[2];
    const float* bias = (const float*)d_in[3];
    float* out = (float*)d_out;

    cudaFuncSetAttribute(gemm_xw_kernel,
                         cudaFuncAttributeMaxDynamicSharedMemorySize, P1_SMEM);
    cudaFuncSetAttribute(lstm_rec_kernel,
                         cudaFuncAttributeMaxDynamicSharedMemorySize, SMEM_P2);

    dim3 g1(G4 / 128, (Bsz * Tlen) / 128);   // (32, 128)
    gemm_xw_kernel<<<g1, 256, P1_SMEM>>>(x, Wih, bias);

    lstm_rec_kernel<<<NBLK, 256, SMEM_P2>>>(Whh, out);
}